// round 8
// baseline (speedup 1.0000x reference)
#include <cuda_runtime.h>
#include <cuda_fp16.h>
#include <math.h>
#include <stdint.h>

#define HDIM 2048
#define IDIM 2048
#define NEXP 16
#define TOPK 4
#define ALPHA 1.702f
#define LIMIT 7.0f
#define T_MAX 4096
#define BM 128
#define BN1 64
#define BN2 128
#define BK 64
#define KC (HDIM/BK)              /* 32 */
#define NSTAGE 3
#define MAX_ROWS (T_MAX*TOPK + NEXP*BM)   /* 18432 */
#define MAX_TILES (MAX_ROWS/BM)           /* 144 */
#define NGROUP 4
#define EPG (NEXP/NGROUP)                 /* 4 experts per group */

// gemm1 smem: A 3x16KB @0, B (gate8KB+up8KB) x3 @49152. total 96KB -> 2 CTA/SM
#define ST_A 16384
#define OFF_B1 49152
#define ST_B1 16384
#define SMEM1 98304
// gemm2 smem: A 3x16KB @0, B 16KB x3 @49152. total 96KB -> 2 CTA/SM
#define OFF_B2 49152
#define ST_B2 16384
#define SMEM2 98304

// ------------------------- scratch (static device) ---------------------------
__device__ __half g_w1h[(size_t)NEXP*HDIM*2*IDIM];   // 268 MB
__device__ __half g_w2h[(size_t)NEXP*IDIM*HDIM];     // 134 MB
__device__ __half g_xh[(size_t)T_MAX*HDIM];          // 16 MB
__device__ __half g_acth[(size_t)MAX_ROWS*IDIM];     // 75 MB
__device__ int   g_topk_idx[T_MAX*TOPK];
__device__ float g_topk_w[T_MAX*TOPK];
__device__ int   g_cnt[NEXP];
__device__ int   g_off[NEXP];
__device__ int   g_cursor[NEXP];
__device__ int   g_pair_tok[MAX_ROWS];
__device__ float g_pair_w[MAX_ROWS];
__device__ int   g_tile_expert[MAX_TILES];

// ------------------------- asm helpers --------------------------------------
__device__ __forceinline__ uint32_t smem_u32(const void* p) {
    uint32_t a;
    asm("{ .reg .u64 t; cvta.to.shared.u64 t, %1; cvt.u32.u64 %0, t; }"
        : "=r"(a) : "l"(p));
    return a;
}
__device__ __forceinline__ uint32_t swzA(uint32_t off) {   // 128B rows
    return off ^ ((off >> 3) & 0x70);
}
__device__ __forceinline__ uint32_t swzB(uint32_t off) {   // 256B rows
    return off ^ (((off >> 8) & 7) << 4);
}
#define CP16(dst, src) \
    asm volatile("cp.async.cg.shared.global [%0], [%1], 16;\n" :: "r"(dst), "l"(src))
#define CP16Z(dst, src, sz) \
    asm volatile("cp.async.cg.shared.global [%0], [%1], 16, %2;\n" :: "r"(dst), "l"(src), "r"(sz))
#define CP_COMMIT() asm volatile("cp.async.commit_group;\n" ::: "memory")
#define CP_WAIT1() asm volatile("cp.async.wait_group 1;\n" ::: "memory")
#define CP_WAIT0() asm volatile("cp.async.wait_group 0;\n" ::: "memory")
#define LDSM4(r0,r1,r2,r3,a) \
    asm volatile("ldmatrix.sync.aligned.m8n8.x4.shared.b16 {%0,%1,%2,%3}, [%4];\n" \
        : "=r"(r0),"=r"(r1),"=r"(r2),"=r"(r3) : "r"(a))
#define LDSM4T(r0,r1,r2,r3,a) \
    asm volatile("ldmatrix.sync.aligned.m8n8.x4.trans.shared.b16 {%0,%1,%2,%3}, [%4];\n" \
        : "=r"(r0),"=r"(r1),"=r"(r2),"=r"(r3) : "r"(a))
#define MMA16816(d, a, b) \
    asm volatile("mma.sync.aligned.m16n8k16.row.col.f32.f16.f16.f32 " \
        "{%0,%1,%2,%3}, {%4,%5,%6,%7}, {%8,%9}, {%0,%1,%2,%3};\n" \
        : "+f"((d)[0]),"+f"((d)[1]),"+f"((d)[2]),"+f"((d)[3]) \
        : "r"((a)[0]),"r"((a)[1]),"r"((a)[2]),"r"((a)[3]), "r"((b)[0]),"r"((b)[1]))

__device__ __forceinline__ float actf(float g, float u) {
    g = fminf(g, LIMIT);
    u = fminf(fmaxf(u, -LIMIT), LIMIT);
    return (u + 1.f) * g / (1.f + expf(-ALPHA * g));
}
__device__ __forceinline__ uint32_t h2bits(float a, float b) {
    __half2 h = __floats2half2_rn(a, b);
    return *reinterpret_cast<uint32_t*>(&h);
}

// ---------------- fp32 -> fp16 conversion ------------------------------------
__global__ void __launch_bounds__(256) cvt_kernel(const float4* __restrict__ src,
                                                  uint2* __restrict__ dst, int n)
{
    int i = blockIdx.x * blockDim.x + threadIdx.x;
    int stride = gridDim.x * blockDim.x;
    for (; i < n; i += stride) {
        float4 v = src[i];
        uint2 o;
        o.x = h2bits(v.x, v.y);
        o.y = h2bits(v.z, v.w);
        dst[i] = o;
    }
}

// ---------------- init: poison maps, zero counters ----------------------------
__global__ void init_kernel()
{
    int i = blockIdx.x * blockDim.x + threadIdx.x;
    if (i < MAX_ROWS) g_pair_tok[i] = -1;
    if (i < MAX_TILES) g_tile_expert[i] = -1;
    if (i < NEXP) g_cnt[i] = 0;
}

// ---------------- router v3: thread = (token, expert) -------------------------
__global__ void __launch_bounds__(256) router_kernel(
    const float* __restrict__ x, const float* __restrict__ rw,
    const float* __restrict__ rb, int T)
{
    int tt = threadIdx.x >> 4;           // 0..15 token within block
    int e  = threadIdx.x & 15;           // expert
    int t = blockIdx.x * 16 + tt;
    if (t >= T) return;

    const float4* xr = (const float4*)(x + (size_t)t * HDIM);
    const float4* wr = (const float4*)(rw + (size_t)e * HDIM);
    float acc = 0.f;
    #pragma unroll 8
    for (int k = 0; k < HDIM/4; k++) {
        float4 a = xr[k], b = wr[k];     // xr dedup across 16 lanes of same token
        acc += a.x*b.x + a.y*b.y + a.z*b.z + a.w*b.w;
    }
    acc += rb[e];

    __shared__ float s_log[16][17];
    s_log[tt][e] = acc;
    __syncthreads();

    if (e == 0) {
        float v[NEXP];
        #pragma unroll
        for (int i = 0; i < NEXP; i++) v[i] = s_log[tt][i];
        int   bi[TOPK];
        float bv[TOPK];
        unsigned used = 0;
        #pragma unroll
        for (int k = 0; k < TOPK; k++) {
            int best = -1; float bval = -INFINITY;
            #pragma unroll
            for (int i = 0; i < NEXP; i++) {
                if (!((used >> i) & 1u) && v[i] > bval) { bval = v[i]; best = i; }
            }
            used |= (1u << best);
            bi[k] = best; bv[k] = bval;
        }
        float m = bv[0];
        float w[TOPK], sum = 0.f;
        #pragma unroll
        for (int k = 0; k < TOPK; k++) { w[k] = expf(bv[k] - m); sum += w[k]; }
        float inv = 1.f / sum;
        #pragma unroll
        for (int k = 0; k < TOPK; k++) {
            g_topk_idx[t*TOPK + k] = bi[k];
            g_topk_w[t*TOPK + k]   = w[k] * inv;
            atomicAdd(&g_cnt[bi[k]], 1);
        }
    }
}

// ---------------- offsets (BM-padded segments) + tile->expert map ------------
__global__ void offsets_kernel()
{
    int off = 0;
    for (int e = 0; e < NEXP; e++) {
        g_off[e] = off;
        g_cursor[e] = off;
        int padded = ((g_cnt[e] + BM - 1) / BM) * BM;
        for (int t = off / BM; t < (off + padded) / BM; t++) g_tile_expert[t] = e;
        off += padded;
    }
}

// ---------------- atomic-cursor compaction ------------------------------------
__global__ void __launch_bounds__(256) fill_kernel(int T)
{
    int i = blockIdx.x * 256 + threadIdx.x;
    if (i >= T * TOPK) return;
    int e = g_topk_idx[i];
    int p = atomicAdd(&g_cursor[e], 1);
    g_pair_tok[p] = i >> 2;
    g_pair_w[p]   = g_topk_w[i];
}

// ---------------- GEMM1 (mma.sync fp16, BN=64, 2 CTA/SM, expert-group) --------
__global__ void __launch_bounds__(256, 2) gemm1_kernel(const float* __restrict__ b1,
                                                       int eglo, int eghi)
{
    int by = blockIdx.y;
    int e = g_tile_expert[by];
    if (e < eglo || e >= eghi) return;
    int n0 = blockIdx.x * BN1;
    int row0 = by * BM;
    int tid = threadIdx.x, lane = tid & 31, wid = tid >> 5;
    int wm = wid & 1, wn = wid >> 1;

    extern __shared__ char smem[];
    uint32_t sb = smem_u32(smem);
    __shared__ int s_tok[BM];
    if (tid < BM) s_tok[tid] = g_pair_tok[row0 + tid];
    __syncthreads();

    const __half* w1e = g_w1h + (size_t)e * HDIM * (2*IDIM);

    auto issue = [&](int kc) {
        int slot = kc % NSTAGE;
        uint32_t abase = sb + slot * ST_A;
        uint32_t gbase = sb + OFF_B1 + slot * ST_B1;
        uint32_t ubase = gbase + 8192;
        int k0 = kc * BK;
        #pragma unroll
        for (int i = 0; i < 4; i++) {
            int id = tid + i * 256;
            int r = id >> 3, c = id & 7;
            int tok = s_tok[r];
            const __half* src = g_xh + (size_t)(tok < 0 ? 0 : tok) * HDIM + k0 + c*8;
            int sz = (tok >= 0) ? 16 : 0;
            CP16Z(abase + swzA((uint32_t)(r*128 + c*16)), src, sz);
        }
        #pragma unroll
        for (int i = 0; i < 2; i++) {
            int id = tid + i * 256;
            int r = id >> 3, c = id & 7;
            const __half* srcg = w1e + (size_t)(k0 + r) * (2*IDIM) + n0 + c*8;
            uint32_t off = swzA((uint32_t)(r*128 + c*16));
            CP16(gbase + off, srcg);
            CP16(ubase + off, srcg + IDIM);
        }
        CP_COMMIT();
    };

    float ag[4][2][4] = {}, au[4][2][4] = {};
    issue(0); issue(1);

    for (int kc = 0; kc < KC; kc++) {
        int slot = kc % NSTAGE;
        if (kc >= KC - 2) { CP_WAIT0(); } else { CP_WAIT1(); }
        __syncthreads();
        uint32_t abase = sb + slot * ST_A;
        uint32_t gbase = sb + OFF_B1 + slot * ST_B1;
        uint32_t ubase = gbase + 8192;
        #pragma unroll
        for (int k16 = 0; k16 < 4; k16++) {
            uint32_t a[4][4];
            #pragma unroll
            for (int mt = 0; mt < 4; mt++) {
                int mrow = wm*64 + mt*16 + (lane & 15);
                uint32_t addr = abase + swzA((uint32_t)(mrow*128 + (k16*2 + (lane>>4))*16));
                LDSM4(a[mt][0], a[mt][1], a[mt][2], a[mt][3], addr);
            }
            uint32_t bg[2][2], bu[2][2];
            {
                int krow = k16*16 + (lane & 15);
                int nh = wn*16 + (lane>>4)*8;
                uint32_t off = swzA((uint32_t)(krow*128 + nh*2));
                uint32_t r0,r1,r2,r3;
                LDSM4T(r0,r1,r2,r3, gbase + off);
                bg[0][0]=r0; bg[0][1]=r1; bg[1][0]=r2; bg[1][1]=r3;
                LDSM4T(r0,r1,r2,r3, ubase + off);
                bu[0][0]=r0; bu[0][1]=r1; bu[1][0]=r2; bu[1][1]=r3;
            }
            #pragma unroll
            for (int mt = 0; mt < 4; mt++)
                #pragma unroll
                for (int nt = 0; nt < 2; nt++) {
                    MMA16816(ag[mt][nt], a[mt], bg[nt]);
                    MMA16816(au[mt][nt], a[mt], bu[nt]);
                }
        }
        if (kc + 2 < KC) issue(kc + 2);
    }

    // epilogue: bias + clip + glu in registers -> half2 stores
    const float* b1e = b1 + (size_t)e * (2*IDIM);
    int r0 = lane >> 2, cc = (lane & 3) * 2;
    #pragma unroll
    for (int nt = 0; nt < 2; nt++) {
        int col = n0 + wn*16 + nt*8 + cc;
        float G0 = b1e[col], G1 = b1e[col+1];
        float U0 = b1e[IDIM + col], U1 = b1e[IDIM + col + 1];
        #pragma unroll
        for (int mt = 0; mt < 4; mt++) {
            int grow = row0 + wm*64 + mt*16;
            float a0 = actf(ag[mt][nt][0] + G0, au[mt][nt][0] + U0);
            float a1 = actf(ag[mt][nt][1] + G1, au[mt][nt][1] + U1);
            float a2 = actf(ag[mt][nt][2] + G0, au[mt][nt][2] + U0);
            float a3 = actf(ag[mt][nt][3] + G1, au[mt][nt][3] + U1);
            __half2 h01 = __floats2half2_rn(a0, a1);
            __half2 h23 = __floats2half2_rn(a2, a3);
            *(__half2*)&g_acth[(size_t)(grow + r0) * IDIM + col]     = h01;
            *(__half2*)&g_acth[(size_t)(grow + r0 + 8) * IDIM + col] = h23;
        }
    }
}

// ---------------- GEMM2 (mma.sync fp16, 3 stages, 2 CTA/SM) -------------------
__global__ void __launch_bounds__(256, 2) gemm2_kernel(const float* __restrict__ b2,
                                                       float* __restrict__ out)
{
    int by = blockIdx.y;
    int e = g_tile_expert[by];
    if (e < 0) return;
    int n0 = blockIdx.x * BN2;
    int row0 = by * BM;
    int tid = threadIdx.x, lane = tid & 31, wid = tid >> 5;
    int wm = wid & 1, wn = wid >> 1;

    extern __shared__ char smem[];
    uint32_t sb = smem_u32(smem);
    __shared__ int   s_tok[BM];
    __shared__ float s_wt[BM];
    if (tid < BM) {
        s_tok[tid] = g_pair_tok[row0 + tid];
        s_wt[tid]  = g_pair_w[row0 + tid];
    }
    __syncthreads();

    const __half* w2e = g_w2h + (size_t)e * IDIM * HDIM;

    auto issue = [&](int kc) {
        int slot = kc % NSTAGE;
        uint32_t abase = sb + slot * ST_A;
        uint32_t bbase = sb + OFF_B2 + slot * ST_B2;
        int k0 = kc * BK;
        #pragma unroll
        for (int i = 0; i < 4; i++) {
            int id = tid + i * 256;
            int r = id >> 3, c = id & 7;
            const __half* src = g_acth + (size_t)(row0 + r) * IDIM + k0 + c*8;
            CP16(abase + swzA((uint32_t)(r*128 + c*16)), src);
        }
        #pragma unroll
        for (int i = 0; i < 4; i++) {
            int id = tid + i * 256;
            int r = id >> 4, c = id & 15;
            const __half* src = w2e + (size_t)(k0 + r) * HDIM + n0 + c*8;
            CP16(bbase + swzB((uint32_t)(r*256 + c*16)), src);
        }
        CP_COMMIT();
    };

    float acc[4][4][4] = {};
    issue(0); issue(1);

    for (int kc = 0; kc < KC; kc++) {
        int slot = kc % NSTAGE;
        if (kc >= KC - 2) { CP_WAIT0(); } else { CP_WAIT1(); }
        __syncthreads();
        uint32_t abase = sb + slot * ST_A;
        uint32_t bbase = sb + OFF_B2 + slot * ST_B2;
        #pragma unroll
        for (int k16 = 0; k16 < 4; k16++) {
            uint32_t a[4][4];
            #pragma unroll
            for (int mt = 0; mt < 4; mt++) {
                int mrow = wm*64 + mt*16 + (lane & 15);
                uint32_t addr = abase + swzA((uint32_t)(mrow*128 + (k16*2 + (lane>>4))*16));
                LDSM4(a[mt][0], a[mt][1], a[mt][2], a[mt][3], addr);
            }
            uint32_t b[4][2];
            #pragma unroll
            for (int h = 0; h < 2; h++) {
                int krow = k16*16 + (lane & 15);
                int nh = wn*32 + h*16 + (lane>>4)*8;
                uint32_t off = swzB((uint32_t)(krow*256 + nh*2));
                uint32_t r0,r1,r2,r3;
                LDSM4T(r0,r1,r2,r3, bbase + off);
                b[h*2][0]=r0; b[h*2][1]=r1; b[h*2+1][0]=r2; b[h*2+1][1]=r3;
            }
            #pragma unroll
            for (int mt = 0; mt < 4; mt++)
                #pragma unroll
                for (int nt = 0; nt < 4; nt++)
                    MMA16816(acc[mt][nt], a[mt], b[nt]);
        }
        if (kc + 2 < KC) issue(kc + 2);
    }

    // epilogue: +bias, *routing weight, atomic scatter by token
    const float* b2e = b2 + (size_t)e * HDIM;
    int r0 = lane >> 2, cc = (lane & 3) * 2;
    #pragma unroll
    for (int mt = 0; mt < 4; mt++) {
        int mrow = wm*64 + mt*16;
        int rA = mrow + r0, rB = rA + 8;
        int tokA = s_tok[rA], tokB = s_tok[rB];
        float wA = s_wt[rA], wB = s_wt[rB];
        #pragma unroll
        for (int nt = 0; nt < 4; nt++) {
            int col = n0 + wn*32 + nt*8 + cc;
            float B0 = b2e[col], B1 = b2e[col+1];
            if (tokA >= 0) {
                atomicAdd(&out[(size_t)tokA * HDIM + col],     (acc[mt][nt][0] + B0) * wA);
                atomicAdd(&out[(size_t)tokA * HDIM + col + 1], (acc[mt][nt][1] + B1) * wA);
            }
            if (tokB >= 0) {
                atomicAdd(&out[(size_t)tokB * HDIM + col],     (acc[mt][nt][2] + B0) * wB);
                atomicAdd(&out[(size_t)tokB * HDIM + col + 1], (acc[mt][nt][3] + B1) * wB);
            }
        }
    }
}

// ---------------- launch ------------------------------------------------------
extern "C" void kernel_launch(void* const* d_in, const int* in_sizes, int n_in,
                              void* d_out, int out_size)
{
    const float* x  = (const float*)d_in[0];
    const float* rw = (const float*)d_in[1];
    const float* rb = (const float*)d_in[2];
    const float* w1 = (const float*)d_in[3];
    const float* b1 = (const float*)d_in[4];
    const float* w2 = (const float*)d_in[5];
    const float* b2 = (const float*)d_in[6];
    float* out = (float*)d_out;

    int T = in_sizes[0] / HDIM;
    if (T > T_MAX) T = T_MAX;

    static cudaStream_t s2 = nullptr;
    static cudaEvent_t evFork = nullptr, ev2 = nullptr;
    static cudaEvent_t evc[NGROUP] = {};
    if (s2 == nullptr) {
        cudaStreamCreateWithFlags(&s2, cudaStreamNonBlocking);
        cudaEventCreateWithFlags(&evFork, cudaEventDisableTiming);
        cudaEventCreateWithFlags(&ev2, cudaEventDisableTiming);
        for (int g = 0; g < NGROUP; g++)
            cudaEventCreateWithFlags(&evc[g], cudaEventDisableTiming);
    }

    cudaFuncSetAttribute(gemm1_kernel, cudaFuncAttributeMaxDynamicSharedMemorySize, SMEM1);
    cudaFuncSetAttribute(gemm2_kernel, cudaFuncAttributeMaxDynamicSharedMemorySize, SMEM2);

    __half *w1h_p, *w2h_p, *xh_p;
    cudaGetSymbolAddress((void**)&w1h_p, g_w1h);
    cudaGetSymbolAddress((void**)&w2h_p, g_w2h);
    cudaGetSymbolAddress((void**)&xh_p, g_xh);

    // ---- fork: x conversion + chunked w1 conversion + w2 on side stream ----
    cudaEventRecord(evFork, 0);
    cudaStreamWaitEvent(s2, evFork, 0);
    cvt_kernel<<<512, 256, 0, s2>>>((const float4*)x, (uint2*)xh_p, T*HDIM/4);
    const int W1CHUNK = NEXP*HDIM*2*IDIM/4 / NGROUP;   // float4 elements per group
    for (int g = 0; g < NGROUP; g++) {
        cvt_kernel<<<1024, 256, 0, s2>>>(
            (const float4*)w1 + (size_t)g*W1CHUNK,
            (uint2*)w1h_p + (size_t)g*W1CHUNK, W1CHUNK);
        cudaEventRecord(evc[g], s2);
    }
    cvt_kernel<<<2048, 256, 0, s2>>>((const float4*)w2, (uint2*)w2h_p, NEXP*IDIM*HDIM/4);
    cudaEventRecord(ev2, s2);

    // ---- main stream: routing chain ----
    cudaMemsetAsync(out, 0, (size_t)T * HDIM * sizeof(float));
    init_kernel<<<(MAX_ROWS + 255)/256, 256>>>();
    router_kernel<<<(T + 15)/16, 256>>>(x, rw, rb, T);
    offsets_kernel<<<1, 1>>>();
    fill_kernel<<<(T*TOPK + 255)/256, 256>>>(T);

    // ---- gemm1 in expert groups, each gated on its weight chunk ----
    for (int g = 0; g < NGROUP; g++) {
        cudaStreamWaitEvent(0, evc[g], 0);
        gemm1_kernel<<<dim3(IDIM/BN1, MAX_TILES), 256, SMEM1>>>(b1, g*EPG, (g+1)*EPG);
    }

    // ---- gemm2 ----
    cudaStreamWaitEvent(0, ev2, 0);
    gemm2_kernel<<<dim3(HDIM/BN2, MAX_TILES), 256, SMEM2>>>(b2, out);
}

// round 9
// speedup vs baseline: 1.2576x; 1.2576x over previous
#include <cuda_runtime.h>
#include <cuda_fp16.h>
#include <math.h>
#include <stdint.h>

#define HDIM 2048
#define IDIM 2048
#define NEXP 16
#define TOPK 4
#define ALPHA 1.702f
#define LIMIT 7.0f
#define T_MAX 4096
#define BM 128
#define BN1 64
#define BN2 128
#define BK 64
#define KC (HDIM/BK)              /* 32 */
#define NSTAGE 3
#define MAX_ROWS (T_MAX*TOPK + NEXP*BM)   /* 18432 */
#define MAX_TILES (MAX_ROWS/BM)           /* 144 */
#define YSPLIT (MAX_TILES/2)              /* 72 */

// gemm1 smem: A 3x16KB @0, B (gate8KB+up8KB) x3 @49152. total 96KB -> 2 CTA/SM
#define ST_A 16384
#define OFF_B1 49152
#define ST_B1 16384
#define SMEM1 98304
// gemm2 smem: A 3x16KB @0, B 16KB x3 @49152. total 96KB -> 2 CTA/SM
#define OFF_B2 49152
#define ST_B2 16384
#define SMEM2 98304

// ------------------------- scratch (static device) ---------------------------
__device__ __half g_w1h[(size_t)NEXP*HDIM*2*IDIM];   // 268 MB
__device__ __half g_w2h[(size_t)NEXP*IDIM*HDIM];     // 134 MB
__device__ __half g_xh[(size_t)T_MAX*HDIM];          // 16 MB
__device__ __half g_acth[(size_t)MAX_ROWS*IDIM];     // 75 MB
__device__ int   g_topk_idx[T_MAX*TOPK];
__device__ float g_topk_w[T_MAX*TOPK];
__device__ int   g_cnt[NEXP];
__device__ int   g_off[NEXP];
__device__ int   g_cursor[NEXP];
__device__ int   g_pair_tok[MAX_ROWS];
__device__ float g_pair_w[MAX_ROWS];
__device__ int   g_tile_expert[MAX_TILES];

// ------------------------- asm helpers --------------------------------------
__device__ __forceinline__ uint32_t smem_u32(const void* p) {
    uint32_t a;
    asm("{ .reg .u64 t; cvta.to.shared.u64 t, %1; cvt.u32.u64 %0, t; }"
        : "=r"(a) : "l"(p));
    return a;
}
__device__ __forceinline__ uint32_t swzA(uint32_t off) {   // 128B rows
    return off ^ ((off >> 3) & 0x70);
}
__device__ __forceinline__ uint32_t swzB(uint32_t off) {   // 256B rows
    return off ^ (((off >> 8) & 7) << 4);
}
#define CP16(dst, src) \
    asm volatile("cp.async.cg.shared.global [%0], [%1], 16;\n" :: "r"(dst), "l"(src))
#define CP16Z(dst, src, sz) \
    asm volatile("cp.async.cg.shared.global [%0], [%1], 16, %2;\n" :: "r"(dst), "l"(src), "r"(sz))
#define CP_COMMIT() asm volatile("cp.async.commit_group;\n" ::: "memory")
#define CP_WAIT1() asm volatile("cp.async.wait_group 1;\n" ::: "memory")
#define CP_WAIT0() asm volatile("cp.async.wait_group 0;\n" ::: "memory")
#define LDSM4(r0,r1,r2,r3,a) \
    asm volatile("ldmatrix.sync.aligned.m8n8.x4.shared.b16 {%0,%1,%2,%3}, [%4];\n" \
        : "=r"(r0),"=r"(r1),"=r"(r2),"=r"(r3) : "r"(a))
#define LDSM4T(r0,r1,r2,r3,a) \
    asm volatile("ldmatrix.sync.aligned.m8n8.x4.trans.shared.b16 {%0,%1,%2,%3}, [%4];\n" \
        : "=r"(r0),"=r"(r1),"=r"(r2),"=r"(r3) : "r"(a))
#define MMA16816(d, a, b) \
    asm volatile("mma.sync.aligned.m16n8k16.row.col.f32.f16.f16.f32 " \
        "{%0,%1,%2,%3}, {%4,%5,%6,%7}, {%8,%9}, {%0,%1,%2,%3};\n" \
        : "+f"((d)[0]),"+f"((d)[1]),"+f"((d)[2]),"+f"((d)[3]) \
        : "r"((a)[0]),"r"((a)[1]),"r"((a)[2]),"r"((a)[3]), "r"((b)[0]),"r"((b)[1]))

__device__ __forceinline__ float actf(float g, float u) {
    g = fminf(g, LIMIT);
    u = fminf(fmaxf(u, -LIMIT), LIMIT);
    return (u + 1.f) * g / (1.f + expf(-ALPHA * g));
}
__device__ __forceinline__ uint32_t h2bits(float a, float b) {
    __half2 h = __floats2half2_rn(a, b);
    return *reinterpret_cast<uint32_t*>(&h);
}

// ---------------- fp32 -> fp16 conversion ------------------------------------
__global__ void __launch_bounds__(256) cvt_kernel(const float4* __restrict__ src,
                                                  uint2* __restrict__ dst, int n)
{
    int i = blockIdx.x * blockDim.x + threadIdx.x;
    int stride = gridDim.x * blockDim.x;
    for (; i < n; i += stride) {
        float4 v = src[i];
        uint2 o;
        o.x = h2bits(v.x, v.y);
        o.y = h2bits(v.z, v.w);
        dst[i] = o;
    }
}

// ---------------- init: poison maps, zero counters ----------------------------
__global__ void init_kernel()
{
    int i = blockIdx.x * blockDim.x + threadIdx.x;
    if (i < MAX_ROWS) g_pair_tok[i] = -1;
    if (i < MAX_TILES) g_tile_expert[i] = -1;
    if (i < NEXP) g_cnt[i] = 0;
}

// ---------------- router v2: warp-per-token (R7, proven) ----------------------
__global__ void __launch_bounds__(256) router_kernel(
    const float* __restrict__ x, const float* __restrict__ rw,
    const float* __restrict__ rb, int T)
{
    int t = blockIdx.x * 8 + (threadIdx.x >> 5);
    int lane = threadIdx.x & 31;
    if (t >= T) return;

    const float4* xr = (const float4*)(x + (size_t)t * HDIM);
    float acc[NEXP];
    #pragma unroll
    for (int e = 0; e < NEXP; e++) acc[e] = 0.f;

    for (int i = 0; i < 16; i++) {
        int idx = i*32 + lane;
        float4 v = xr[idx];
        uint2 o;
        o.x = h2bits(v.x, v.y);
        o.y = h2bits(v.z, v.w);
        *(uint2*)&g_xh[(size_t)t*HDIM + idx*4] = o;
        #pragma unroll
        for (int e = 0; e < NEXP; e++) {
            float4 w = ((const float4*)(rw + (size_t)e*HDIM))[idx];
            acc[e] += v.x*w.x + v.y*w.y + v.z*w.z + v.w*w.w;
        }
    }
    #pragma unroll
    for (int e = 0; e < NEXP; e++) {
        #pragma unroll
        for (int s = 16; s > 0; s >>= 1)
            acc[e] += __shfl_xor_sync(0xffffffffu, acc[e], s);
    }

    if (lane == 0) {
        float v[NEXP];
        #pragma unroll
        for (int e = 0; e < NEXP; e++) v[e] = acc[e] + rb[e];
        int   bi[TOPK];
        float bv[TOPK];
        unsigned used = 0;
        #pragma unroll
        for (int k = 0; k < TOPK; k++) {
            int best = -1; float bval = -INFINITY;
            #pragma unroll
            for (int i = 0; i < NEXP; i++) {
                if (!((used >> i) & 1u) && v[i] > bval) { bval = v[i]; best = i; }
            }
            used |= (1u << best);
            bi[k] = best; bv[k] = bval;
        }
        float m = bv[0];
        float w[TOPK], sum = 0.f;
        #pragma unroll
        for (int k = 0; k < TOPK; k++) { w[k] = expf(bv[k] - m); sum += w[k]; }
        float inv = 1.f / sum;
        #pragma unroll
        for (int k = 0; k < TOPK; k++) {
            g_topk_idx[t*TOPK + k] = bi[k];
            g_topk_w[t*TOPK + k]   = w[k] * inv;
            atomicAdd(&g_cnt[bi[k]], 1);
        }
    }
}

// ---------------- offsets (BM-padded segments) + tile->expert map ------------
__global__ void offsets_kernel()
{
    int off = 0;
    for (int e = 0; e < NEXP; e++) {
        g_off[e] = off;
        g_cursor[e] = off;
        int padded = ((g_cnt[e] + BM - 1) / BM) * BM;
        for (int t = off / BM; t < (off + padded) / BM; t++) g_tile_expert[t] = e;
        off += padded;
    }
}

// ---------------- atomic-cursor compaction ------------------------------------
__global__ void __launch_bounds__(256) fill_kernel(int T)
{
    int i = blockIdx.x * 256 + threadIdx.x;
    if (i >= T * TOPK) return;
    int e = g_topk_idx[i];
    int p = atomicAdd(&g_cursor[e], 1);
    g_pair_tok[p] = i >> 2;
    g_pair_w[p]   = g_topk_w[i];
}

// ---------------- GEMM1 (mma.sync fp16, BN=64, 2 CTA/SM) ----------------------
__global__ void __launch_bounds__(256, 2) gemm1_kernel(const float* __restrict__ b1,
                                                       int y0)
{
    int by = blockIdx.y + y0;
    int e = g_tile_expert[by];
    if (e < 0) return;
    int n0 = blockIdx.x * BN1;
    int row0 = by * BM;
    int tid = threadIdx.x, lane = tid & 31, wid = tid >> 5;
    int wm = wid & 1, wn = wid >> 1;

    extern __shared__ char smem[];
    uint32_t sb = smem_u32(smem);
    __shared__ int s_tok[BM];
    if (tid < BM) s_tok[tid] = g_pair_tok[row0 + tid];
    __syncthreads();

    const __half* w1e = g_w1h + (size_t)e * HDIM * (2*IDIM);

    auto issue = [&](int kc) {
        int slot = kc % NSTAGE;
        uint32_t abase = sb + slot * ST_A;
        uint32_t gbase = sb + OFF_B1 + slot * ST_B1;
        uint32_t ubase = gbase + 8192;
        int k0 = kc * BK;
        #pragma unroll
        for (int i = 0; i < 4; i++) {
            int id = tid + i * 256;
            int r = id >> 3, c = id & 7;
            int tok = s_tok[r];
            const __half* src = g_xh + (size_t)(tok < 0 ? 0 : tok) * HDIM + k0 + c*8;
            int sz = (tok >= 0) ? 16 : 0;
            CP16Z(abase + swzA((uint32_t)(r*128 + c*16)), src, sz);
        }
        #pragma unroll
        for (int i = 0; i < 2; i++) {
            int id = tid + i * 256;
            int r = id >> 3, c = id & 7;
            const __half* srcg = w1e + (size_t)(k0 + r) * (2*IDIM) + n0 + c*8;
            uint32_t off = swzA((uint32_t)(r*128 + c*16));
            CP16(gbase + off, srcg);
            CP16(ubase + off, srcg + IDIM);
        }
        CP_COMMIT();
    };

    float ag[4][2][4] = {}, au[4][2][4] = {};
    issue(0); issue(1);

    for (int kc = 0; kc < KC; kc++) {
        int slot = kc % NSTAGE;
        if (kc >= KC - 2) { CP_WAIT0(); } else { CP_WAIT1(); }
        __syncthreads();
        uint32_t abase = sb + slot * ST_A;
        uint32_t gbase = sb + OFF_B1 + slot * ST_B1;
        uint32_t ubase = gbase + 8192;
        #pragma unroll
        for (int k16 = 0; k16 < 4; k16++) {
            uint32_t a[4][4];
            #pragma unroll
            for (int mt = 0; mt < 4; mt++) {
                int mrow = wm*64 + mt*16 + (lane & 15);
                uint32_t addr = abase + swzA((uint32_t)(mrow*128 + (k16*2 + (lane>>4))*16));
                LDSM4(a[mt][0], a[mt][1], a[mt][2], a[mt][3], addr);
            }
            uint32_t bg[2][2], bu[2][2];
            {
                int krow = k16*16 + (lane & 15);
                int nh = wn*16 + (lane>>4)*8;
                uint32_t off = swzA((uint32_t)(krow*128 + nh*2));
                uint32_t r0,r1,r2,r3;
                LDSM4T(r0,r1,r2,r3, gbase + off);
                bg[0][0]=r0; bg[0][1]=r1; bg[1][0]=r2; bg[1][1]=r3;
                LDSM4T(r0,r1,r2,r3, ubase + off);
                bu[0][0]=r0; bu[0][1]=r1; bu[1][0]=r2; bu[1][1]=r3;
            }
            #pragma unroll
            for (int mt = 0; mt < 4; mt++)
                #pragma unroll
                for (int nt = 0; nt < 2; nt++) {
                    MMA16816(ag[mt][nt], a[mt], bg[nt]);
                    MMA16816(au[mt][nt], a[mt], bu[nt]);
                }
        }
        if (kc + 2 < KC) issue(kc + 2);
    }

    // epilogue: bias + clip + glu in registers -> half2 stores
    const float* b1e = b1 + (size_t)e * (2*IDIM);
    int r0 = lane >> 2, cc = (lane & 3) * 2;
    #pragma unroll
    for (int nt = 0; nt < 2; nt++) {
        int col = n0 + wn*16 + nt*8 + cc;
        float G0 = b1e[col], G1 = b1e[col+1];
        float U0 = b1e[IDIM + col], U1 = b1e[IDIM + col + 1];
        #pragma unroll
        for (int mt = 0; mt < 4; mt++) {
            int grow = row0 + wm*64 + mt*16;
            float a0 = actf(ag[mt][nt][0] + G0, au[mt][nt][0] + U0);
            float a1 = actf(ag[mt][nt][1] + G1, au[mt][nt][1] + U1);
            float a2 = actf(ag[mt][nt][2] + G0, au[mt][nt][2] + U0);
            float a3 = actf(ag[mt][nt][3] + G1, au[mt][nt][3] + U1);
            __half2 h01 = __floats2half2_rn(a0, a1);
            __half2 h23 = __floats2half2_rn(a2, a3);
            *(__half2*)&g_acth[(size_t)(grow + r0) * IDIM + col]     = h01;
            *(__half2*)&g_acth[(size_t)(grow + r0 + 8) * IDIM + col] = h23;
        }
    }
}

// ---------------- GEMM2 (mma.sync fp16, 3 stages, 2 CTA/SM) -------------------
__global__ void __launch_bounds__(256, 2) gemm2_kernel(const float* __restrict__ b2,
                                                       float* __restrict__ out, int y0)
{
    int by = blockIdx.y + y0;
    int e = g_tile_expert[by];
    if (e < 0) return;
    int n0 = blockIdx.x * BN2;
    int row0 = by * BM;
    int tid = threadIdx.x, lane = tid & 31, wid = tid >> 5;
    int wm = wid & 1, wn = wid >> 1;

    extern __shared__ char smem[];
    uint32_t sb = smem_u32(smem);
    __shared__ int   s_tok[BM];
    __shared__ float s_wt[BM];
    if (tid < BM) {
        s_tok[tid] = g_pair_tok[row0 + tid];
        s_wt[tid]  = g_pair_w[row0 + tid];
    }
    __syncthreads();

    const __half* w2e = g_w2h + (size_t)e * IDIM * HDIM;

    auto issue = [&](int kc) {
        int slot = kc % NSTAGE;
        uint32_t abase = sb + slot * ST_A;
        uint32_t bbase = sb + OFF_B2 + slot * ST_B2;
        int k0 = kc * BK;
        #pragma unroll
        for (int i = 0; i < 4; i++) {
            int id = tid + i * 256;
            int r = id >> 3, c = id & 7;
            const __half* src = g_acth + (size_t)(row0 + r) * IDIM + k0 + c*8;
            CP16(abase + swzA((uint32_t)(r*128 + c*16)), src);
        }
        #pragma unroll
        for (int i = 0; i < 4; i++) {
            int id = tid + i * 256;
            int r = id >> 4, c = id & 15;
            const __half* src = w2e + (size_t)(k0 + r) * HDIM + n0 + c*8;
            CP16(bbase + swzB((uint32_t)(r*256 + c*16)), src);
        }
        CP_COMMIT();
    };

    float acc[4][4][4] = {};
    issue(0); issue(1);

    for (int kc = 0; kc < KC; kc++) {
        int slot = kc % NSTAGE;
        if (kc >= KC - 2) { CP_WAIT0(); } else { CP_WAIT1(); }
        __syncthreads();
        uint32_t abase = sb + slot * ST_A;
        uint32_t bbase = sb + OFF_B2 + slot * ST_B2;
        #pragma unroll
        for (int k16 = 0; k16 < 4; k16++) {
            uint32_t a[4][4];
            #pragma unroll
            for (int mt = 0; mt < 4; mt++) {
                int mrow = wm*64 + mt*16 + (lane & 15);
                uint32_t addr = abase + swzA((uint32_t)(mrow*128 + (k16*2 + (lane>>4))*16));
                LDSM4(a[mt][0], a[mt][1], a[mt][2], a[mt][3], addr);
            }
            uint32_t b[4][2];
            #pragma unroll
            for (int h = 0; h < 2; h++) {
                int krow = k16*16 + (lane & 15);
                int nh = wn*32 + h*16 + (lane>>4)*8;
                uint32_t off = swzB((uint32_t)(krow*256 + nh*2));
                uint32_t r0,r1,r2,r3;
                LDSM4T(r0,r1,r2,r3, bbase + off);
                b[h*2][0]=r0; b[h*2][1]=r1; b[h*2+1][0]=r2; b[h*2+1][1]=r3;
            }
            #pragma unroll
            for (int mt = 0; mt < 4; mt++)
                #pragma unroll
                for (int nt = 0; nt < 4; nt++)
                    MMA16816(acc[mt][nt], a[mt], b[nt]);
        }
        if (kc + 2 < KC) issue(kc + 2);
    }

    // epilogue: +bias, *routing weight, atomic scatter by token
    const float* b2e = b2 + (size_t)e * HDIM;
    int r0 = lane >> 2, cc = (lane & 3) * 2;
    #pragma unroll
    for (int mt = 0; mt < 4; mt++) {
        int mrow = wm*64 + mt*16;
        int rA = mrow + r0, rB = rA + 8;
        int tokA = s_tok[rA], tokB = s_tok[rB];
        float wA = s_wt[rA], wB = s_wt[rB];
        #pragma unroll
        for (int nt = 0; nt < 4; nt++) {
            int col = n0 + wn*32 + nt*8 + cc;
            float B0 = b2e[col], B1 = b2e[col+1];
            if (tokA >= 0) {
                atomicAdd(&out[(size_t)tokA * HDIM + col],     (acc[mt][nt][0] + B0) * wA);
                atomicAdd(&out[(size_t)tokA * HDIM + col + 1], (acc[mt][nt][1] + B1) * wA);
            }
            if (tokB >= 0) {
                atomicAdd(&out[(size_t)tokB * HDIM + col],     (acc[mt][nt][2] + B0) * wB);
                atomicAdd(&out[(size_t)tokB * HDIM + col + 1], (acc[mt][nt][3] + B1) * wB);
            }
        }
    }
}

// ---------------- launch ------------------------------------------------------
extern "C" void kernel_launch(void* const* d_in, const int* in_sizes, int n_in,
                              void* d_out, int out_size)
{
    const float* x  = (const float*)d_in[0];
    const float* rw = (const float*)d_in[1];
    const float* rb = (const float*)d_in[2];
    const float* w1 = (const float*)d_in[3];
    const float* b1 = (const float*)d_in[4];
    const float* w2 = (const float*)d_in[5];
    const float* b2 = (const float*)d_in[6];
    float* out = (float*)d_out;

    int T = in_sizes[0] / HDIM;
    if (T > T_MAX) T = T_MAX;

    static cudaStream_t s2 = nullptr;
    static cudaEvent_t evFork = nullptr, ev1 = nullptr, ev2 = nullptr;
    static cudaEvent_t evA = nullptr, evB = nullptr, evDone = nullptr;
    if (s2 == nullptr) {
        cudaStreamCreateWithFlags(&s2, cudaStreamNonBlocking);
        cudaEventCreateWithFlags(&evFork, cudaEventDisableTiming);
        cudaEventCreateWithFlags(&ev1, cudaEventDisableTiming);
        cudaEventCreateWithFlags(&ev2, cudaEventDisableTiming);
        cudaEventCreateWithFlags(&evA, cudaEventDisableTiming);
        cudaEventCreateWithFlags(&evB, cudaEventDisableTiming);
        cudaEventCreateWithFlags(&evDone, cudaEventDisableTiming);
    }

    cudaFuncSetAttribute(gemm1_kernel, cudaFuncAttributeMaxDynamicSharedMemorySize, SMEM1);
    cudaFuncSetAttribute(gemm2_kernel, cudaFuncAttributeMaxDynamicSharedMemorySize, SMEM2);

    __half *w1h_p, *w2h_p;
    cudaGetSymbolAddress((void**)&w1h_p, g_w1h);
    cudaGetSymbolAddress((void**)&w2h_p, g_w2h);

    // ---- fork: weight conversion on side stream ----
    cudaEventRecord(evFork, 0);
    cudaStreamWaitEvent(s2, evFork, 0);
    cvt_kernel<<<2048, 256, 0, s2>>>((const float4*)w1, (uint2*)w1h_p, NEXP*HDIM*2*IDIM/4);
    cudaEventRecord(ev1, s2);
    cvt_kernel<<<2048, 256, 0, s2>>>((const float4*)w2, (uint2*)w2h_p, NEXP*IDIM*HDIM/4);

    // ---- main stream: routing chain ----
    cudaMemsetAsync(out, 0, (size_t)T * HDIM * sizeof(float));
    init_kernel<<<(MAX_ROWS + 255)/256, 256>>>();
    router_kernel<<<(T + 7)/8, 256>>>(x, rw, rb, T);
    offsets_kernel<<<1, 1>>>();
    fill_kernel<<<(T*TOPK + 255)/256, 256>>>(T);

    // ---- pipelined GEMMs: gemm1 halves on main, gemm2 halves on s2 ----
    cudaStreamWaitEvent(0, ev1, 0);
    gemm1_kernel<<<dim3(IDIM/BN1, YSPLIT), 256, SMEM1>>>(b1, 0);
    cudaEventRecord(evA, 0);
    gemm1_kernel<<<dim3(IDIM/BN1, MAX_TILES - YSPLIT), 256, SMEM1>>>(b1, YSPLIT);
    cudaEventRecord(evB, 0);

    // s2 already ordered after w2 cvt (in-stream)
    cudaStreamWaitEvent(s2, evA, 0);
    gemm2_kernel<<<dim3(HDIM/BN2, YSPLIT), 256, SMEM2, s2>>>(b2, out, 0);
    cudaStreamWaitEvent(s2, evB, 0);
    gemm2_kernel<<<dim3(HDIM/BN2, MAX_TILES - YSPLIT), 256, SMEM2, s2>>>(b2, out, YSPLIT);
    cudaEventRecord(evDone, s2);

    // ---- join side stream back into origin stream (capture requires it) ----
    cudaStreamWaitEvent(0, evDone, 0);
}

// round 10
// speedup vs baseline: 1.2726x; 1.0119x over previous
#include <cuda_runtime.h>
#include <cuda_fp16.h>
#include <math.h>
#include <stdint.h>

#define HDIM 2048
#define IDIM 2048
#define NEXP 16
#define TOPK 4
#define ALPHA 1.702f
#define LIMIT 7.0f
#define T_MAX 4096
#define BM 128
#define BN1 64
#define BN2 128
#define BK 64
#define KC (HDIM/BK)              /* 32 */
#define NSTAGE 3
#define MAX_ROWS (T_MAX*TOPK + NEXP*BM)   /* 18432 */
#define MAX_TILES (MAX_ROWS/BM)           /* 144 */
#define RCHUNK 512                         /* router smem chunk (floats/expert) */

// gemm1 smem: A 3x16KB @0, B (gate8KB+up8KB) x3 @49152. total 96KB -> 2 CTA/SM
#define ST_A 16384
#define OFF_B1 49152
#define ST_B1 16384
#define SMEM1 98304
// gemm2 smem: A 3x16KB @0, B 16KB x3 @49152. total 96KB -> 2 CTA/SM
#define OFF_B2 49152
#define ST_B2 16384
#define SMEM2 98304

// ------------------------- scratch (static device) ---------------------------
__device__ __half g_w1h[(size_t)NEXP*HDIM*2*IDIM];   // 268 MB
__device__ __half g_w2h[(size_t)NEXP*IDIM*HDIM];     // 134 MB
__device__ __half g_xh[(size_t)T_MAX*HDIM];          // 16 MB
__device__ __half g_acth[(size_t)MAX_ROWS*IDIM];     // 75 MB
__device__ int   g_topk_idx[T_MAX*TOPK];
__device__ float g_topk_w[T_MAX*TOPK];
__device__ int   g_cnt[NEXP];
__device__ int   g_off[NEXP];
__device__ int   g_cursor[NEXP];
__device__ int   g_pair_tok[MAX_ROWS];
__device__ float g_pair_w[MAX_ROWS];
__device__ int   g_tile_expert[MAX_TILES];

// ------------------------- asm helpers --------------------------------------
__device__ __forceinline__ uint32_t smem_u32(const void* p) {
    uint32_t a;
    asm("{ .reg .u64 t; cvta.to.shared.u64 t, %1; cvt.u32.u64 %0, t; }"
        : "=r"(a) : "l"(p));
    return a;
}
__device__ __forceinline__ uint32_t swzA(uint32_t off) {   // 128B rows
    return off ^ ((off >> 3) & 0x70);
}
__device__ __forceinline__ uint32_t swzB(uint32_t off) {   // 256B rows
    return off ^ (((off >> 8) & 7) << 4);
}
#define CP16(dst, src) \
    asm volatile("cp.async.cg.shared.global [%0], [%1], 16;\n" :: "r"(dst), "l"(src))
#define CP16Z(dst, src, sz) \
    asm volatile("cp.async.cg.shared.global [%0], [%1], 16, %2;\n" :: "r"(dst), "l"(src), "r"(sz))
#define CP_COMMIT() asm volatile("cp.async.commit_group;\n" ::: "memory")
#define CP_WAIT1() asm volatile("cp.async.wait_group 1;\n" ::: "memory")
#define CP_WAIT0() asm volatile("cp.async.wait_group 0;\n" ::: "memory")
#define LDSM4(r0,r1,r2,r3,a) \
    asm volatile("ldmatrix.sync.aligned.m8n8.x4.shared.b16 {%0,%1,%2,%3}, [%4];\n" \
        : "=r"(r0),"=r"(r1),"=r"(r2),"=r"(r3) : "r"(a))
#define LDSM4T(r0,r1,r2,r3,a) \
    asm volatile("ldmatrix.sync.aligned.m8n8.x4.trans.shared.b16 {%0,%1,%2,%3}, [%4];\n" \
        : "=r"(r0),"=r"(r1),"=r"(r2),"=r"(r3) : "r"(a))
#define MMA16816(d, a, b) \
    asm volatile("mma.sync.aligned.m16n8k16.row.col.f32.f16.f16.f32 " \
        "{%0,%1,%2,%3}, {%4,%5,%6,%7}, {%8,%9}, {%0,%1,%2,%3};\n" \
        : "+f"((d)[0]),"+f"((d)[1]),"+f"((d)[2]),"+f"((d)[3]) \
        : "r"((a)[0]),"r"((a)[1]),"r"((a)[2]),"r"((a)[3]), "r"((b)[0]),"r"((b)[1]))

__device__ __forceinline__ float actf(float g, float u) {
    g = fminf(g, LIMIT);
    u = fminf(fmaxf(u, -LIMIT), LIMIT);
    return (u + 1.f) * g / (1.f + expf(-ALPHA * g));
}
__device__ __forceinline__ uint32_t h2bits(float a, float b) {
    __half2 h = __floats2half2_rn(a, b);
    return *reinterpret_cast<uint32_t*>(&h);
}

// ---------------- fp32 -> fp16 conversion ------------------------------------
__global__ void __launch_bounds__(256) cvt_kernel(const float4* __restrict__ src,
                                                  uint2* __restrict__ dst, int n)
{
    int i = blockIdx.x * blockDim.x + threadIdx.x;
    int stride = gridDim.x * blockDim.x;
    for (; i < n; i += stride) {
        float4 v = src[i];
        uint2 o;
        o.x = h2bits(v.x, v.y);
        o.y = h2bits(v.z, v.w);
        dst[i] = o;
    }
}

// ---------------- init: poison maps, zero counters ----------------------------
__global__ void init_kernel()
{
    int i = blockIdx.x * blockDim.x + threadIdx.x;
    if (i < MAX_ROWS) g_pair_tok[i] = -1;
    if (i < MAX_TILES) g_tile_expert[i] = -1;
    if (i < NEXP) g_cnt[i] = 0;
}

// ---------------- router v4: warp-per-token + SMEM-staged rw -----------------
__global__ void __launch_bounds__(256) router_kernel(
    const float* __restrict__ x, const float* __restrict__ rw,
    const float* __restrict__ rb, int T)
{
    __shared__ float s_w[NEXP][RCHUNK];   // 32 KB
    int wid = threadIdx.x >> 5, lane = threadIdx.x & 31;
    int t = blockIdx.x * 8 + wid;
    const float4* xr = (const float4*)(x + (size_t)(t < T ? t : 0) * HDIM);

    float acc[NEXP];
    #pragma unroll
    for (int e = 0; e < NEXP; e++) acc[e] = 0.f;

    for (int c = 0; c < HDIM/RCHUNK; c++) {        // 4 chunks
        __syncthreads();
        // cooperative rw chunk load: 16 experts x 128 float4
        for (int i = threadIdx.x; i < NEXP*(RCHUNK/4); i += 256) {
            int e = i >> 7, col = i & 127;
            ((float4*)s_w[e])[col] =
                ((const float4*)(rw + (size_t)e*HDIM + c*RCHUNK))[col];
        }
        __syncthreads();
        if (t < T) {
            #pragma unroll
            for (int j = 0; j < RCHUNK/4/32; j++) {   // 4 float4 per lane
                int idx = j*32 + lane;
                float4 v = xr[c*(RCHUNK/4) + idx];
                uint2 o;
                o.x = h2bits(v.x, v.y);
                o.y = h2bits(v.z, v.w);
                *(uint2*)&g_xh[(size_t)t*HDIM + (c*(RCHUNK/4) + idx)*4] = o;
                #pragma unroll
                for (int e = 0; e < NEXP; e++) {
                    float4 w = ((const float4*)s_w[e])[idx];
                    acc[e] += v.x*w.x + v.y*w.y + v.z*w.z + v.w*w.w;
                }
            }
        }
    }
    if (t >= T) return;
    #pragma unroll
    for (int e = 0; e < NEXP; e++) {
        #pragma unroll
        for (int s = 16; s > 0; s >>= 1)
            acc[e] += __shfl_xor_sync(0xffffffffu, acc[e], s);
    }

    if (lane == 0) {
        float v[NEXP];
        #pragma unroll
        for (int e = 0; e < NEXP; e++) v[e] = acc[e] + rb[e];
        int   bi[TOPK];
        float bv[TOPK];
        unsigned used = 0;
        #pragma unroll
        for (int k = 0; k < TOPK; k++) {
            int best = -1; float bval = -INFINITY;
            #pragma unroll
            for (int i = 0; i < NEXP; i++) {
                if (!((used >> i) & 1u) && v[i] > bval) { bval = v[i]; best = i; }
            }
            used |= (1u << best);
            bi[k] = best; bv[k] = bval;
        }
        float m = bv[0];
        float w[TOPK], sum = 0.f;
        #pragma unroll
        for (int k = 0; k < TOPK; k++) { w[k] = expf(bv[k] - m); sum += w[k]; }
        float inv = 1.f / sum;
        #pragma unroll
        for (int k = 0; k < TOPK; k++) {
            g_topk_idx[t*TOPK + k] = bi[k];
            g_topk_w[t*TOPK + k]   = w[k] * inv;
            atomicAdd(&g_cnt[bi[k]], 1);
        }
    }
}

// ---------------- offsets (BM-padded segments) + tile->expert map ------------
__global__ void offsets_kernel()
{
    int off = 0;
    for (int e = 0; e < NEXP; e++) {
        g_off[e] = off;
        g_cursor[e] = off;
        int padded = ((g_cnt[e] + BM - 1) / BM) * BM;
        for (int t = off / BM; t < (off + padded) / BM; t++) g_tile_expert[t] = e;
        off += padded;
    }
}

// ---------------- atomic-cursor compaction ------------------------------------
__global__ void __launch_bounds__(256) fill_kernel(int T)
{
    int i = blockIdx.x * 256 + threadIdx.x;
    if (i >= T * TOPK) return;
    int e = g_topk_idx[i];
    int p = atomicAdd(&g_cursor[e], 1);
    g_pair_tok[p] = i >> 2;
    g_pair_w[p]   = g_topk_w[i];
}

// ---------------- GEMM1 (mma.sync fp16, BN=64, 2 CTA/SM, expert window) -------
__global__ void __launch_bounds__(256, 2) gemm1_kernel(const float* __restrict__ b1,
                                                       int eglo, int eghi)
{
    int by = blockIdx.y;
    int e = g_tile_expert[by];
    if (e < eglo || e >= eghi) return;
    int n0 = blockIdx.x * BN1;
    int row0 = by * BM;
    int tid = threadIdx.x, lane = tid & 31, wid = tid >> 5;
    int wm = wid & 1, wn = wid >> 1;

    extern __shared__ char smem[];
    uint32_t sb = smem_u32(smem);
    __shared__ int s_tok[BM];
    if (tid < BM) s_tok[tid] = g_pair_tok[row0 + tid];
    __syncthreads();

    const __half* w1e = g_w1h + (size_t)e * HDIM * (2*IDIM);

    auto issue = [&](int kc) {
        int slot = kc % NSTAGE;
        uint32_t abase = sb + slot * ST_A;
        uint32_t gbase = sb + OFF_B1 + slot * ST_B1;
        uint32_t ubase = gbase + 8192;
        int k0 = kc * BK;
        #pragma unroll
        for (int i = 0; i < 4; i++) {
            int id = tid + i * 256;
            int r = id >> 3, c = id & 7;
            int tok = s_tok[r];
            const __half* src = g_xh + (size_t)(tok < 0 ? 0 : tok) * HDIM + k0 + c*8;
            int sz = (tok >= 0) ? 16 : 0;
            CP16Z(abase + swzA((uint32_t)(r*128 + c*16)), src, sz);
        }
        #pragma unroll
        for (int i = 0; i < 2; i++) {
            int id = tid + i * 256;
            int r = id >> 3, c = id & 7;
            const __half* srcg = w1e + (size_t)(k0 + r) * (2*IDIM) + n0 + c*8;
            uint32_t off = swzA((uint32_t)(r*128 + c*16));
            CP16(gbase + off, srcg);
            CP16(ubase + off, srcg + IDIM);
        }
        CP_COMMIT();
    };

    float ag[4][2][4] = {}, au[4][2][4] = {};
    issue(0); issue(1);

    for (int kc = 0; kc < KC; kc++) {
        int slot = kc % NSTAGE;
        if (kc >= KC - 2) { CP_WAIT0(); } else { CP_WAIT1(); }
        __syncthreads();
        uint32_t abase = sb + slot * ST_A;
        uint32_t gbase = sb + OFF_B1 + slot * ST_B1;
        uint32_t ubase = gbase + 8192;
        #pragma unroll
        for (int k16 = 0; k16 < 4; k16++) {
            uint32_t a[4][4];
            #pragma unroll
            for (int mt = 0; mt < 4; mt++) {
                int mrow = wm*64 + mt*16 + (lane & 15);
                uint32_t addr = abase + swzA((uint32_t)(mrow*128 + (k16*2 + (lane>>4))*16));
                LDSM4(a[mt][0], a[mt][1], a[mt][2], a[mt][3], addr);
            }
            uint32_t bg[2][2], bu[2][2];
            {
                int krow = k16*16 + (lane & 15);
                int nh = wn*16 + (lane>>4)*8;
                uint32_t off = swzA((uint32_t)(krow*128 + nh*2));
                uint32_t r0,r1,r2,r3;
                LDSM4T(r0,r1,r2,r3, gbase + off);
                bg[0][0]=r0; bg[0][1]=r1; bg[1][0]=r2; bg[1][1]=r3;
                LDSM4T(r0,r1,r2,r3, ubase + off);
                bu[0][0]=r0; bu[0][1]=r1; bu[1][0]=r2; bu[1][1]=r3;
            }
            #pragma unroll
            for (int mt = 0; mt < 4; mt++)
                #pragma unroll
                for (int nt = 0; nt < 2; nt++) {
                    MMA16816(ag[mt][nt], a[mt], bg[nt]);
                    MMA16816(au[mt][nt], a[mt], bu[nt]);
                }
        }
        if (kc + 2 < KC) issue(kc + 2);
    }

    // epilogue: bias + clip + glu in registers -> half2 stores
    const float* b1e = b1 + (size_t)e * (2*IDIM);
    int r0 = lane >> 2, cc = (lane & 3) * 2;
    #pragma unroll
    for (int nt = 0; nt < 2; nt++) {
        int col = n0 + wn*16 + nt*8 + cc;
        float G0 = b1e[col], G1 = b1e[col+1];
        float U0 = b1e[IDIM + col], U1 = b1e[IDIM + col + 1];
        #pragma unroll
        for (int mt = 0; mt < 4; mt++) {
            int grow = row0 + wm*64 + mt*16;
            float a0 = actf(ag[mt][nt][0] + G0, au[mt][nt][0] + U0);
            float a1 = actf(ag[mt][nt][1] + G1, au[mt][nt][1] + U1);
            float a2 = actf(ag[mt][nt][2] + G0, au[mt][nt][2] + U0);
            float a3 = actf(ag[mt][nt][3] + G1, au[mt][nt][3] + U1);
            __half2 h01 = __floats2half2_rn(a0, a1);
            __half2 h23 = __floats2half2_rn(a2, a3);
            *(__half2*)&g_acth[(size_t)(grow + r0) * IDIM + col]     = h01;
            *(__half2*)&g_acth[(size_t)(grow + r0 + 8) * IDIM + col] = h23;
        }
    }
}

// ---------------- GEMM2 (mma.sync fp16, 3 stages, 2 CTA/SM) -------------------
__global__ void __launch_bounds__(256, 2) gemm2_kernel(const float* __restrict__ b2,
                                                       float* __restrict__ out)
{
    int by = blockIdx.y;
    int e = g_tile_expert[by];
    if (e < 0) return;
    int n0 = blockIdx.x * BN2;
    int row0 = by * BM;
    int tid = threadIdx.x, lane = tid & 31, wid = tid >> 5;
    int wm = wid & 1, wn = wid >> 1;

    extern __shared__ char smem[];
    uint32_t sb = smem_u32(smem);
    __shared__ int   s_tok[BM];
    __shared__ float s_wt[BM];
    if (tid < BM) {
        s_tok[tid] = g_pair_tok[row0 + tid];
        s_wt[tid]  = g_pair_w[row0 + tid];
    }
    __syncthreads();

    const __half* w2e = g_w2h + (size_t)e * IDIM * HDIM;

    auto issue = [&](int kc) {
        int slot = kc % NSTAGE;
        uint32_t abase = sb + slot * ST_A;
        uint32_t bbase = sb + OFF_B2 + slot * ST_B2;
        int k0 = kc * BK;
        #pragma unroll
        for (int i = 0; i < 4; i++) {
            int id = tid + i * 256;
            int r = id >> 3, c = id & 7;
            const __half* src = g_acth + (size_t)(row0 + r) * IDIM + k0 + c*8;
            CP16(abase + swzA((uint32_t)(r*128 + c*16)), src);
        }
        #pragma unroll
        for (int i = 0; i < 4; i++) {
            int id = tid + i * 256;
            int r = id >> 4, c = id & 15;
            const __half* src = w2e + (size_t)(k0 + r) * HDIM + n0 + c*8;
            CP16(bbase + swzB((uint32_t)(r*256 + c*16)), src);
        }
        CP_COMMIT();
    };

    float acc[4][4][4] = {};
    issue(0); issue(1);

    for (int kc = 0; kc < KC; kc++) {
        int slot = kc % NSTAGE;
        if (kc >= KC - 2) { CP_WAIT0(); } else { CP_WAIT1(); }
        __syncthreads();
        uint32_t abase = sb + slot * ST_A;
        uint32_t bbase = sb + OFF_B2 + slot * ST_B2;
        #pragma unroll
        for (int k16 = 0; k16 < 4; k16++) {
            uint32_t a[4][4];
            #pragma unroll
            for (int mt = 0; mt < 4; mt++) {
                int mrow = wm*64 + mt*16 + (lane & 15);
                uint32_t addr = abase + swzA((uint32_t)(mrow*128 + (k16*2 + (lane>>4))*16));
                LDSM4(a[mt][0], a[mt][1], a[mt][2], a[mt][3], addr);
            }
            uint32_t b[4][2];
            #pragma unroll
            for (int h = 0; h < 2; h++) {
                int krow = k16*16 + (lane & 15);
                int nh = wn*32 + h*16 + (lane>>4)*8;
                uint32_t off = swzB((uint32_t)(krow*256 + nh*2));
                uint32_t r0,r1,r2,r3;
                LDSM4T(r0,r1,r2,r3, bbase + off);
                b[h*2][0]=r0; b[h*2][1]=r1; b[h*2+1][0]=r2; b[h*2+1][1]=r3;
            }
            #pragma unroll
            for (int mt = 0; mt < 4; mt++)
                #pragma unroll
                for (int nt = 0; nt < 4; nt++)
                    MMA16816(acc[mt][nt], a[mt], b[nt]);
        }
        if (kc + 2 < KC) issue(kc + 2);
    }

    // epilogue: +bias, *routing weight, atomic scatter by token
    const float* b2e = b2 + (size_t)e * HDIM;
    int r0 = lane >> 2, cc = (lane & 3) * 2;
    #pragma unroll
    for (int mt = 0; mt < 4; mt++) {
        int mrow = wm*64 + mt*16;
        int rA = mrow + r0, rB = rA + 8;
        int tokA = s_tok[rA], tokB = s_tok[rB];
        float wA = s_wt[rA], wB = s_wt[rB];
        #pragma unroll
        for (int nt = 0; nt < 4; nt++) {
            int col = n0 + wn*32 + nt*8 + cc;
            float B0 = b2e[col], B1 = b2e[col+1];
            if (tokA >= 0) {
                atomicAdd(&out[(size_t)tokA * HDIM + col],     (acc[mt][nt][0] + B0) * wA);
                atomicAdd(&out[(size_t)tokA * HDIM + col + 1], (acc[mt][nt][1] + B1) * wA);
            }
            if (tokB >= 0) {
                atomicAdd(&out[(size_t)tokB * HDIM + col],     (acc[mt][nt][2] + B0) * wB);
                atomicAdd(&out[(size_t)tokB * HDIM + col + 1], (acc[mt][nt][3] + B1) * wB);
            }
        }
    }
}

// ---------------- launch ------------------------------------------------------
extern "C" void kernel_launch(void* const* d_in, const int* in_sizes, int n_in,
                              void* d_out, int out_size)
{
    const float* x  = (const float*)d_in[0];
    const float* rw = (const float*)d_in[1];
    const float* rb = (const float*)d_in[2];
    const float* w1 = (const float*)d_in[3];
    const float* b1 = (const float*)d_in[4];
    const float* w2 = (const float*)d_in[5];
    const float* b2 = (const float*)d_in[6];
    float* out = (float*)d_out;

    int T = in_sizes[0] / HDIM;
    if (T > T_MAX) T = T_MAX;

    static cudaStream_t s2 = nullptr;
    static cudaEvent_t evFork = nullptr, evc0 = nullptr, evc1 = nullptr, ev2 = nullptr;
    if (s2 == nullptr) {
        cudaStreamCreateWithFlags(&s2, cudaStreamNonBlocking);
        cudaEventCreateWithFlags(&evFork, cudaEventDisableTiming);
        cudaEventCreateWithFlags(&evc0, cudaEventDisableTiming);
        cudaEventCreateWithFlags(&evc1, cudaEventDisableTiming);
        cudaEventCreateWithFlags(&ev2, cudaEventDisableTiming);
    }

    cudaFuncSetAttribute(gemm1_kernel, cudaFuncAttributeMaxDynamicSharedMemorySize, SMEM1);
    cudaFuncSetAttribute(gemm2_kernel, cudaFuncAttributeMaxDynamicSharedMemorySize, SMEM2);

    __half *w1h_p, *w2h_p;
    cudaGetSymbolAddress((void**)&w1h_p, g_w1h);
    cudaGetSymbolAddress((void**)&w2h_p, g_w2h);

    // ---- fork: chunked w1 conversion (2 expert groups) + w2 on side stream ----
    cudaEventRecord(evFork, 0);
    cudaStreamWaitEvent(s2, evFork, 0);
    const int W1HALF = NEXP*HDIM*2*IDIM/4 / 2;   // float4 elems for experts 0..7
    cvt_kernel<<<1536, 256, 0, s2>>>((const float4*)w1, (uint2*)w1h_p, W1HALF);
    cudaEventRecord(evc0, s2);
    cvt_kernel<<<1536, 256, 0, s2>>>((const float4*)w1 + W1HALF,
                                     (uint2*)w1h_p + W1HALF, W1HALF);
    cudaEventRecord(evc1, s2);
    cvt_kernel<<<2048, 256, 0, s2>>>((const float4*)w2, (uint2*)w2h_p, NEXP*IDIM*HDIM/4);
    cudaEventRecord(ev2, s2);

    // ---- main stream: routing chain ----
    cudaMemsetAsync(out, 0, (size_t)T * HDIM * sizeof(float));
    init_kernel<<<(MAX_ROWS + 255)/256, 256>>>();
    router_kernel<<<(T + 7)/8, 256>>>(x, rw, rb, T);
    offsets_kernel<<<1, 1>>>();
    fill_kernel<<<(T*TOPK + 255)/256, 256>>>(T);

    // ---- gemm1 gated per expert half ----
    cudaStreamWaitEvent(0, evc0, 0);
    gemm1_kernel<<<dim3(IDIM/BN1, MAX_TILES), 256, SMEM1>>>(b1, 0, NEXP/2);
    cudaStreamWaitEvent(0, evc1, 0);
    gemm1_kernel<<<dim3(IDIM/BN1, MAX_TILES), 256, SMEM1>>>(b1, NEXP/2, NEXP);

    // ---- gemm2 ----
    cudaStreamWaitEvent(0, ev2, 0);
    gemm2_kernel<<<dim3(HDIM/BN2, MAX_TILES), 256, SMEM2>>>(b2, out);
}